// round 2
// baseline (speedup 1.0000x reference)
#include <cuda_runtime.h>

// Problem constants: B=4, C=256, H=W=64, K=7, GROUPS=16, GC=16, CR=64
#define HW   4096
#define WDIM 64

typedef unsigned long long ull;

// Scratch for conv1 output x: [4][64][4096] fp32 = 4 MB
__device__ float g_xbuf[4 * 64 * 4096];

__device__ __forceinline__ ull pack2(float lo, float hi) {
    ull r;
    asm("mov.b64 %0, {%1, %2};" : "=l"(r) : "f"(lo), "f"(hi));
    return r;
}
__device__ __forceinline__ void unpack2(ull v, float &lo, float &hi) {
    asm("mov.b64 {%0, %1}, %2;" : "=f"(lo), "=f"(hi) : "l"(v));
}
__device__ __forceinline__ void fma2(ull &d, ull a, ull b) {
    asm("fma.rn.f32x2 %0, %1, %2, %0;" : "+l"(d) : "l"(a), "l"(b));
}

// ---------------------------------------------------------------------------
// Kernel 1: conv1 (1x1, 256->64) + BN + ReLU -> g_xbuf   (unchanged from R1)
// ---------------------------------------------------------------------------
__global__ __launch_bounds__(256, 1)
void conv1_kernel(const float* __restrict__ guide,
                  const float* __restrict__ w1,
                  const float* __restrict__ gamma,
                  const float* __restrict__ beta,
                  const float* __restrict__ mean,
                  const float* __restrict__ var)
{
    __shared__ float w1t[64 * 68];
    __shared__ float gsh[64 * 68];

    const int tid   = threadIdx.x;
    const int b     = blockIdx.y;
    const int gpix0 = blockIdx.x * 64;
    const int mq = tid >> 4, pq = tid & 15;
    const int m0 = mq * 4,   p0 = pq * 4;

    ull acc[4][2];
    #pragma unroll
    for (int i = 0; i < 4; i++) { acc[i][0] = 0ull; acc[i][1] = 0ull; }

    for (int r0 = 0; r0 < 256; r0 += 64) {
        #pragma unroll
        for (int i = tid; i < 4096; i += 256) {
            int m = i >> 6, rr = i & 63;
            w1t[rr * 68 + m] = w1[m * 256 + r0 + rr];
        }
        #pragma unroll
        for (int i = tid; i < 1024; i += 256) {
            int rr = i >> 4, px4 = (i & 15) * 4;
            *(float4*)&gsh[rr * 68 + px4] =
                *(const float4*)&guide[(b * 256 + r0 + rr) * HW + gpix0 + px4];
        }
        __syncthreads();

        #pragma unroll 8
        for (int rr = 0; rr < 64; rr++) {
            float4 w4 = *(const float4*)&w1t[rr * 68 + m0];
            ulonglong2 xv = *(const ulonglong2*)&gsh[rr * 68 + p0];
            ull wp;
            wp = pack2(w4.x, w4.x); fma2(acc[0][0], xv.x, wp); fma2(acc[0][1], xv.y, wp);
            wp = pack2(w4.y, w4.y); fma2(acc[1][0], xv.x, wp); fma2(acc[1][1], xv.y, wp);
            wp = pack2(w4.z, w4.z); fma2(acc[2][0], xv.x, wp); fma2(acc[2][1], xv.y, wp);
            wp = pack2(w4.w, w4.w); fma2(acc[3][0], xv.x, wp); fma2(acc[3][1], xv.y, wp);
        }
        __syncthreads();
    }

    #pragma unroll
    for (int i = 0; i < 4; i++) {
        int m = m0 + i;
        float inv = gamma[m] * rsqrtf(var[m] + 1e-5f);
        float bsh = beta[m] - mean[m] * inv;
        float v0, v1, v2, v3;
        unpack2(acc[i][0], v0, v1);
        unpack2(acc[i][1], v2, v3);
        v0 = fmaxf(fmaf(v0, inv, bsh), 0.f);
        v1 = fmaxf(fmaf(v1, inv, bsh), 0.f);
        v2 = fmaxf(fmaf(v2, inv, bsh), 0.f);
        v3 = fmaxf(fmaf(v3, inv, bsh), 0.f);
        *(float4*)&g_xbuf[(b * 64 + m) * HW + gpix0 + p0] = make_float4(v0, v1, v2, v3);
    }
}

// ---------------------------------------------------------------------------
// Kernel 2: fused conv2 + 7x7 dynamic aggregation + residual.
// One (group, 16x16 tile, batch) per CTA. 512 threads (16 warps), 1 CTA/SM.
// smem: x[64][256] + f[16][22][28] + w2dup(ull)[64][60] + wgt[49][256] = 181.5 KB
// ---------------------------------------------------------------------------
#define FSTRIDE 28
#define FCH     (22 * FSTRIDE)   // 616 floats per channel
#define W2S     60               // ull stride per r-row

__global__ __launch_bounds__(512, 1)
void fused_kernel(const float* __restrict__ feat,
                  const float* __restrict__ w2,
                  const float* __restrict__ b2,
                  float* __restrict__ out)
{
    extern __shared__ float smem[];
    float* x_sh   = smem;                          // 64*256 = 16384 f
    float* f_sh   = x_sh + 64 * 256;               // 16*616 = 9856 f
    ull*   w2d    = (ull*)(f_sh + 16 * FCH);       // 64*60 ull = 30720 B
    float* wgt_sh = (float*)(w2d + 64 * W2S);      // 49*256 = 12544 f

    const int tid  = threadIdx.x;
    const int g    = blockIdx.x;
    const int tile = blockIdx.y;
    const int b    = blockIdx.z;
    const int y0 = (tile >> 2) * 16;
    const int x0 = (tile & 3) * 16;

    // ---- stage x tile: x_sh[r][row*16+col]
    #pragma unroll 2
    for (int i = tid; i < 64 * 64; i += 512) {
        int r = i >> 6;
        int p4 = i & 63;
        int row = p4 >> 2, c4 = (p4 & 3) * 4;
        *(float4*)&x_sh[r * 256 + row * 16 + c4] =
            *(const float4*)&g_xbuf[(b * 64 + r) * HW + (y0 + row) * WDIM + x0 + c4];
    }

    // ---- stage feature tile with 3-px halo, zero padded: f_sh[c][yy][xx]
    for (int i = tid; i < 16 * 484; i += 512) {
        int c = i / 484;
        int rem = i - c * 484;
        int yy = rem / 22;
        int xx = rem - yy * 22;
        int gy = y0 + yy - 3, gx = x0 + xx - 3;
        float v = 0.f;
        if ((unsigned)gy < 64u && (unsigned)gx < 64u)
            v = feat[(b * 256 + g * 16 + c) * HW + gy * WDIM + gx];
        f_sh[c * FCH + yy * FSTRIDE + xx] = v;
    }

    // ---- stage w2 for this group, pre-duplicated as f32x2 pairs: w2d[r][kq*8+kk]
    for (int i = tid; i < 49 * 64; i += 512) {
        int k = i >> 6, r = i & 63;
        int kqi = k / 7, kki = k - kqi * 7;
        float v = w2[(g * 49 + k) * 64 + r];
        w2d[r * W2S + kqi * 8 + kki] = pack2(v, v);
    }
    __syncthreads();

    // -------- Phase 1: dynamic-weight GEMM  wgt[49][256] = w2_g @ x + b2
    // 448 active threads: kq = tid>>6 (0..6), pq = tid&63 -> 7 k x 4 px tile
    {
        const int kq = tid >> 6, pq = tid & 63;
        if (kq < 7) {
            ull acc[7][2];
            #pragma unroll
            for (int kk = 0; kk < 7; kk++) {
                float bv = b2[g * 49 + kq * 7 + kk];
                ull bp = pack2(bv, bv);
                acc[kk][0] = bp; acc[kk][1] = bp;
            }
            const float* xp0 = &x_sh[pq * 4];
            const ull*   wp0 = &w2d[kq * 8];
            #pragma unroll 4
            for (int r = 0; r < 64; r++) {
                ulonglong2 xv = *(const ulonglong2*)(xp0 + r * 256);
                ulonglong2 w01 = *(const ulonglong2*)(wp0 + r * W2S);
                ulonglong2 w23 = *(const ulonglong2*)(wp0 + r * W2S + 2);
                ulonglong2 w45 = *(const ulonglong2*)(wp0 + r * W2S + 4);
                ull w6 = *(wp0 + r * W2S + 6);
                fma2(acc[0][0], xv.x, w01.x); fma2(acc[0][1], xv.y, w01.x);
                fma2(acc[1][0], xv.x, w01.y); fma2(acc[1][1], xv.y, w01.y);
                fma2(acc[2][0], xv.x, w23.x); fma2(acc[2][1], xv.y, w23.x);
                fma2(acc[3][0], xv.x, w23.y); fma2(acc[3][1], xv.y, w23.y);
                fma2(acc[4][0], xv.x, w45.x); fma2(acc[4][1], xv.y, w45.x);
                fma2(acc[5][0], xv.x, w45.y); fma2(acc[5][1], xv.y, w45.y);
                fma2(acc[6][0], xv.x, w6);    fma2(acc[6][1], xv.y, w6);
            }
            #pragma unroll
            for (int kk = 0; kk < 7; kk++) {
                int k = kq * 7 + kk;
                ull* dst = (ull*)&wgt_sh[k * 256 + pq * 4];
                dst[0] = acc[kk][0]; dst[1] = acc[kk][1];
            }
        }
    }
    __syncthreads();

    // -------- Phase 2: 7x7 dynamic aggregation + residual
    // 512 threads: ch = tid>>5 (0..15), rowA = (tid>>1)&15, half = tid&1 -> 8 px
    {
        const int c    = tid >> 5;
        const int rowA = (tid >> 1) & 15;
        const int xbase = (tid & 1) * 8;

        float acc[8];
        #pragma unroll
        for (int j = 0; j < 8; j++) acc[j] = 0.f;

        const float* fbase = &f_sh[c * FCH + xbase];
        const float* wbase = &wgt_sh[rowA * 16 + xbase];

        #pragma unroll 1
        for (int di = 0; di < 7; di++) {
            float fr[16];
            #pragma unroll
            for (int q = 0; q < 4; q++)
                *(float4*)&fr[q * 4] =
                    *(const float4*)(fbase + (rowA + di) * FSTRIDE + q * 4);
            #pragma unroll
            for (int dj = 0; dj < 7; dj++) {
                int k = di * 7 + dj;
                float wv[8];
                *(float4*)&wv[0] = *(const float4*)(wbase + k * 256);
                *(float4*)&wv[4] = *(const float4*)(wbase + k * 256 + 4);
                #pragma unroll
                for (int j = 0; j < 8; j++)
                    acc[j] = fmaf(wv[j], fr[j + dj], acc[j]);
            }
        }
        // residual + store
        #pragma unroll
        for (int j = 0; j < 8; j++)
            acc[j] += fbase[(rowA + 3) * FSTRIDE + j + 3];

        float* op = &out[(b * 256 + g * 16 + c) * HW + (y0 + rowA) * WDIM + x0 + xbase];
        *(float4*)(op)     = make_float4(acc[0], acc[1], acc[2], acc[3]);
        *(float4*)(op + 4) = make_float4(acc[4], acc[5], acc[6], acc[7]);
    }
}

// ---------------------------------------------------------------------------
extern "C" void kernel_launch(void* const* d_in, const int* in_sizes, int n_in,
                              void* d_out, int out_size)
{
    const float* feat  = (const float*)d_in[0];
    const float* guide = (const float*)d_in[1];
    const float* w1    = (const float*)d_in[2];
    const float* gamma = (const float*)d_in[3];
    const float* beta  = (const float*)d_in[4];
    const float* mean  = (const float*)d_in[5];
    const float* var   = (const float*)d_in[6];
    const float* w2    = (const float*)d_in[7];
    const float* b2    = (const float*)d_in[8];
    float* out = (float*)d_out;

    conv1_kernel<<<dim3(64, 4), 256>>>(guide, w1, gamma, beta, mean, var);

    const int smem_bytes = (64 * 256 + 16 * FCH + 49 * 256) * 4 + 64 * W2S * 8;
    cudaFuncSetAttribute(fused_kernel,
                         cudaFuncAttributeMaxDynamicSharedMemorySize, smem_bytes);
    fused_kernel<<<dim3(16, 16, 4), 512, smem_bytes>>>(feat, w2, b2, out);
}

// round 3
// speedup vs baseline: 1.1809x; 1.1809x over previous
#include <cuda_runtime.h>

// Problem constants: B=4, C=256, H=W=64, K=7, GROUPS=16, GC=16, CR=64
#define HW   4096
#define WDIM 64

typedef unsigned long long ull;

// Scratch for conv1 output x: [4][64][4096] fp32 = 4 MB
__device__ float g_xbuf[4 * 64 * 4096];

__device__ __forceinline__ ull pack2(float lo, float hi) {
    ull r;
    asm("mov.b64 %0, {%1, %2};" : "=l"(r) : "f"(lo), "f"(hi));
    return r;
}
__device__ __forceinline__ void unpack2(ull v, float &lo, float &hi) {
    asm("mov.b64 {%0, %1}, %2;" : "=f"(lo), "=f"(hi) : "l"(v));
}
__device__ __forceinline__ void fma2(ull &d, ull a, ull b) {
    asm("fma.rn.f32x2 %0, %1, %2, %0;" : "+l"(d) : "l"(a), "l"(b));
}

// ---------------------------------------------------------------------------
// Kernel 1: conv1 (1x1, 256->64) + BN + ReLU -> g_xbuf
// ---------------------------------------------------------------------------
__global__ __launch_bounds__(256, 1)
void conv1_kernel(const float* __restrict__ guide,
                  const float* __restrict__ w1,
                  const float* __restrict__ gamma,
                  const float* __restrict__ beta,
                  const float* __restrict__ mean,
                  const float* __restrict__ var)
{
    __shared__ float w1t[64 * 68];
    __shared__ float gsh[64 * 68];

    const int tid   = threadIdx.x;
    const int b     = blockIdx.y;
    const int gpix0 = blockIdx.x * 64;
    const int mq = tid >> 4, pq = tid & 15;
    const int m0 = mq * 4,   p0 = pq * 4;

    ull acc[4][2];
    #pragma unroll
    for (int i = 0; i < 4; i++) { acc[i][0] = 0ull; acc[i][1] = 0ull; }

    for (int r0 = 0; r0 < 256; r0 += 64) {
        #pragma unroll
        for (int i = tid; i < 4096; i += 256) {
            int m = i >> 6, rr = i & 63;
            w1t[rr * 68 + m] = w1[m * 256 + r0 + rr];
        }
        #pragma unroll
        for (int i = tid; i < 1024; i += 256) {
            int rr = i >> 4, px4 = (i & 15) * 4;
            *(float4*)&gsh[rr * 68 + px4] =
                *(const float4*)&guide[(b * 256 + r0 + rr) * HW + gpix0 + px4];
        }
        __syncthreads();

        #pragma unroll 8
        for (int rr = 0; rr < 64; rr++) {
            float4 w4 = *(const float4*)&w1t[rr * 68 + m0];
            ulonglong2 xv = *(const ulonglong2*)&gsh[rr * 68 + p0];
            ull wp;
            wp = pack2(w4.x, w4.x); fma2(acc[0][0], xv.x, wp); fma2(acc[0][1], xv.y, wp);
            wp = pack2(w4.y, w4.y); fma2(acc[1][0], xv.x, wp); fma2(acc[1][1], xv.y, wp);
            wp = pack2(w4.z, w4.z); fma2(acc[2][0], xv.x, wp); fma2(acc[2][1], xv.y, wp);
            wp = pack2(w4.w, w4.w); fma2(acc[3][0], xv.x, wp); fma2(acc[3][1], xv.y, wp);
        }
        __syncthreads();
    }

    #pragma unroll
    for (int i = 0; i < 4; i++) {
        int m = m0 + i;
        float inv = gamma[m] * rsqrtf(var[m] + 1e-5f);
        float bsh = beta[m] - mean[m] * inv;
        float v0, v1, v2, v3;
        unpack2(acc[i][0], v0, v1);
        unpack2(acc[i][1], v2, v3);
        v0 = fmaxf(fmaf(v0, inv, bsh), 0.f);
        v1 = fmaxf(fmaf(v1, inv, bsh), 0.f);
        v2 = fmaxf(fmaf(v2, inv, bsh), 0.f);
        v3 = fmaxf(fmaf(v3, inv, bsh), 0.f);
        *(float4*)&g_xbuf[(b * 64 + m) * HW + gpix0 + p0] = make_float4(v0, v1, v2, v3);
    }
}

// ---------------------------------------------------------------------------
// Kernel 2: fused conv2 + 7x7 dynamic aggregation + residual.
// One (group, 16x16 tile, batch) per CTA; 512 threads; conflict-free smem.
//  Phase 1: 14 warps, warp = (kq, px-half); lane tile 7k x 4px.
//           x loads conflict-free, w2 loads warp-uniform broadcast.
//  Phase 2: warp = pixel row, lane = (xhalf, channel).
//           wgt reads broadcast; f reads conflict-free via channel stride 620.
// ---------------------------------------------------------------------------
#define FCH 620                 // f_sh channel stride (620/4 = 155 odd -> no conflicts)
#define FRS 28                  // f_sh row stride

__global__ __launch_bounds__(512, 1)
void fused_kernel(const float* __restrict__ feat,
                  const float* __restrict__ w2,
                  const float* __restrict__ b2,
                  float* __restrict__ out)
{
    extern __shared__ float smem[];
    float* x_sh   = smem;                          // 64*256 f      = 65536 B
    float* f_sh   = x_sh + 64 * 256;               // 16*620 f      = 39680 B
    ull*   w2d    = (ull*)(f_sh + 16 * FCH);       // 64*64 ull     = 32768 B
    float* wgt_sh = (float*)(w2d + 64 * 64);       // 49*256 f      = 50176 B
                                                   // total 188160 B

    const int tid  = threadIdx.x;
    const int g    = blockIdx.x;
    const int tile = blockIdx.y;
    const int b    = blockIdx.z;
    const int y0 = (tile >> 2) * 16;
    const int x0 = (tile & 3) * 16;
    const int w    = tid >> 5;
    const int lane = tid & 31;

    // ---- stage x tile: x_sh[r][row*16+col]
    #pragma unroll 2
    for (int i = tid; i < 64 * 64; i += 512) {
        int r = i >> 6;
        int p4 = i & 63;
        int row = p4 >> 2, c4 = (p4 & 3) * 4;
        *(float4*)&x_sh[r * 256 + row * 16 + c4] =
            *(const float4*)&g_xbuf[(b * 64 + r) * HW + (y0 + row) * WDIM + x0 + c4];
    }

    // ---- stage feature tile with 3-px halo: f_sh[c*620 + yy*28 + xx]
    for (int i = tid; i < 16 * 484; i += 512) {
        int c = i / 484;
        int rem = i - c * 484;
        int yy = rem / 22;
        int xx = rem - yy * 22;
        int gy = y0 + yy - 3, gx = x0 + xx - 3;
        float v = 0.f;
        if ((unsigned)gy < 64u && (unsigned)gx < 64u)
            v = feat[(b * 256 + g * 16 + c) * HW + gy * WDIM + gx];
        f_sh[c * FCH + yy * FRS + xx] = v;
    }

    // ---- stage w2, pre-duplicated f32x2: w2d[r*64 + (k/7)*8 + k%7]
    for (int i = tid; i < 49 * 64; i += 512) {
        int k = i >> 6, r = i & 63;
        int kqi = k / 7, kki = k - kqi * 7;
        float v = w2[(g * 49 + k) * 64 + r];
        w2d[r * 64 + kqi * 8 + kki] = pack2(v, v);
    }
    __syncthreads();

    // -------- Phase 1: dynamic-weight GEMM  wgt[49][256] = w2_g @ x + b2
    if (w < 14) {
        const int kq = w >> 1;                 // 0..6
        const int p0 = (w & 1) * 128 + lane * 4;  // 4-px chunk, conflict-free

        ull acc[7][2];
        #pragma unroll
        for (int kk = 0; kk < 7; kk++) {
            float bv = b2[g * 49 + kq * 7 + kk];
            ull bp = pack2(bv, bv);
            acc[kk][0] = bp; acc[kk][1] = bp;
        }
        const float* xp0 = &x_sh[p0];
        const ull*   wp0 = &w2d[kq * 8];
        #pragma unroll 4
        for (int r = 0; r < 64; r++) {
            ulonglong2 xv  = *(const ulonglong2*)(xp0 + r * 256);
            ulonglong2 w01 = *(const ulonglong2*)(wp0 + r * 64);
            ulonglong2 w23 = *(const ulonglong2*)(wp0 + r * 64 + 2);
            ulonglong2 w45 = *(const ulonglong2*)(wp0 + r * 64 + 4);
            ull        w6  = *(wp0 + r * 64 + 6);
            fma2(acc[0][0], xv.x, w01.x); fma2(acc[0][1], xv.y, w01.x);
            fma2(acc[1][0], xv.x, w01.y); fma2(acc[1][1], xv.y, w01.y);
            fma2(acc[2][0], xv.x, w23.x); fma2(acc[2][1], xv.y, w23.x);
            fma2(acc[3][0], xv.x, w23.y); fma2(acc[3][1], xv.y, w23.y);
            fma2(acc[4][0], xv.x, w45.x); fma2(acc[4][1], xv.y, w45.x);
            fma2(acc[5][0], xv.x, w45.y); fma2(acc[5][1], xv.y, w45.y);
            fma2(acc[6][0], xv.x, w6);    fma2(acc[6][1], xv.y, w6);
        }
        #pragma unroll
        for (int kk = 0; kk < 7; kk++) {
            int k = kq * 7 + kk;
            ull* dst = (ull*)&wgt_sh[k * 256 + p0];
            dst[0] = acc[kk][0]; dst[1] = acc[kk][1];   // STS.128, conflict-free
        }
    }
    __syncthreads();

    // -------- Phase 2: 7x7 dynamic aggregation + residual
    // warp = pixel row; lane = xhalf*16 + c; each lane: 8 px x 1 channel
    {
        const int rowA = w;
        const int c    = lane & 15;
        const int xb   = (lane >> 4) * 8;

        const float* fbase = f_sh + c * FCH + xb;
        const float* wbase = wgt_sh + rowA * 16 + xb;

        float acc[8];
        #pragma unroll
        for (int j = 0; j < 8; j++) acc[j] = 0.f;

        #pragma unroll 1
        for (int di = 0; di < 7; di++) {
            float fr[16];
            #pragma unroll
            for (int q = 0; q < 4; q++)
                *(float4*)&fr[q * 4] =
                    *(const float4*)(fbase + (rowA + di) * FRS + q * 4);
            #pragma unroll
            for (int dj = 0; dj < 7; dj++) {
                int k = di * 7 + dj;
                float wv[8];
                *(float4*)&wv[0] = *(const float4*)(wbase + k * 256);      // broadcast
                *(float4*)&wv[4] = *(const float4*)(wbase + k * 256 + 4);  // broadcast
                #pragma unroll
                for (int j = 0; j < 8; j++)
                    acc[j] = fmaf(wv[j], fr[j + dj], acc[j]);
            }
        }
        // residual + store
        #pragma unroll
        for (int j = 0; j < 8; j++)
            acc[j] += fbase[(rowA + 3) * FRS + j + 3];

        float* op = &out[(b * 256 + g * 16 + c) * HW + (y0 + rowA) * WDIM + x0 + xb];
        *(float4*)(op)     = make_float4(acc[0], acc[1], acc[2], acc[3]);
        *(float4*)(op + 4) = make_float4(acc[4], acc[5], acc[6], acc[7]);
    }
}

// ---------------------------------------------------------------------------
extern "C" void kernel_launch(void* const* d_in, const int* in_sizes, int n_in,
                              void* d_out, int out_size)
{
    const float* feat  = (const float*)d_in[0];
    const float* guide = (const float*)d_in[1];
    const float* w1    = (const float*)d_in[2];
    const float* gamma = (const float*)d_in[3];
    const float* beta  = (const float*)d_in[4];
    const float* mean  = (const float*)d_in[5];
    const float* var   = (const float*)d_in[6];
    const float* w2    = (const float*)d_in[7];
    const float* b2    = (const float*)d_in[8];
    float* out = (float*)d_out;

    conv1_kernel<<<dim3(64, 4), 256>>>(guide, w1, gamma, beta, mean, var);

    const int smem_bytes = (64 * 256 + 16 * FCH + 49 * 256) * 4 + 64 * 64 * 8; // 188160
    cudaFuncSetAttribute(fused_kernel,
                         cudaFuncAttributeMaxDynamicSharedMemorySize, smem_bytes);
    fused_kernel<<<dim3(16, 16, 4), 512, smem_bytes>>>(feat, w2, b2, out);
}

// round 4
// speedup vs baseline: 1.4871x; 1.2593x over previous
#include <cuda_runtime.h>

// Problem constants: B=4, C=256, H=W=64, K=7, GROUPS=16, GC=16, CR=64
#define HW   4096
#define WDIM 64

typedef unsigned long long ull;

// Scratch for conv1 output x: [4][64][4096] fp32 = 4 MB
__device__ float g_xbuf[4 * 64 * 4096];

__device__ __forceinline__ ull pack2(float lo, float hi) {
    ull r;
    asm("mov.b64 %0, {%1, %2};" : "=l"(r) : "f"(lo), "f"(hi));
    return r;
}
__device__ __forceinline__ void unpack2(ull v, float &lo, float &hi) {
    asm("mov.b64 {%0, %1}, %2;" : "=f"(lo), "=f"(hi) : "l"(v));
}
__device__ __forceinline__ void fma2(ull &d, ull a, ull b) {
    asm("fma.rn.f32x2 %0, %1, %2, %0;" : "+l"(d) : "l"(a), "l"(b));
}
__device__ __forceinline__ unsigned smem_u32(const void* p) {
    return (unsigned)__cvta_generic_to_shared(p);
}
__device__ __forceinline__ void cp_async16(unsigned dst, const void* src) {
    asm volatile("cp.async.cg.shared.global [%0], [%1], 16;" :: "r"(dst), "l"(src));
}
__device__ __forceinline__ void cp_async4z(unsigned dst, const void* src, int sz) {
    asm volatile("cp.async.ca.shared.global [%0], [%1], 4, %2;"
                 :: "r"(dst), "l"(src), "r"(sz));
}
__device__ __forceinline__ void cp_commit() {
    asm volatile("cp.async.commit_group;");
}

// ---------------------------------------------------------------------------
// Kernel 1: conv1 (1x1, 256->64) + BN + ReLU -> g_xbuf
// ---------------------------------------------------------------------------
__global__ __launch_bounds__(256, 1)
void conv1_kernel(const float* __restrict__ guide,
                  const float* __restrict__ w1,
                  const float* __restrict__ gamma,
                  const float* __restrict__ beta,
                  const float* __restrict__ mean,
                  const float* __restrict__ var)
{
    __shared__ float w1t[64 * 68];
    __shared__ float gsh[64 * 68];

    const int tid   = threadIdx.x;
    const int b     = blockIdx.y;
    const int gpix0 = blockIdx.x * 64;
    const int mq = tid >> 4, pq = tid & 15;
    const int m0 = mq * 4,   p0 = pq * 4;

    ull acc[4][2];
    #pragma unroll
    for (int i = 0; i < 4; i++) { acc[i][0] = 0ull; acc[i][1] = 0ull; }

    for (int r0 = 0; r0 < 256; r0 += 64) {
        #pragma unroll
        for (int i = tid; i < 4096; i += 256) {
            int m = i >> 6, rr = i & 63;
            w1t[rr * 68 + m] = w1[m * 256 + r0 + rr];
        }
        #pragma unroll
        for (int i = tid; i < 1024; i += 256) {
            int rr = i >> 4, px4 = (i & 15) * 4;
            *(float4*)&gsh[rr * 68 + px4] =
                *(const float4*)&guide[(b * 256 + r0 + rr) * HW + gpix0 + px4];
        }
        __syncthreads();

        #pragma unroll 8
        for (int rr = 0; rr < 64; rr++) {
            float4 w4 = *(const float4*)&w1t[rr * 68 + m0];
            ulonglong2 xv = *(const ulonglong2*)&gsh[rr * 68 + p0];
            ull wp;
            wp = pack2(w4.x, w4.x); fma2(acc[0][0], xv.x, wp); fma2(acc[0][1], xv.y, wp);
            wp = pack2(w4.y, w4.y); fma2(acc[1][0], xv.x, wp); fma2(acc[1][1], xv.y, wp);
            wp = pack2(w4.z, w4.z); fma2(acc[2][0], xv.x, wp); fma2(acc[2][1], xv.y, wp);
            wp = pack2(w4.w, w4.w); fma2(acc[3][0], xv.x, wp); fma2(acc[3][1], xv.y, wp);
        }
        __syncthreads();
    }

    #pragma unroll
    for (int i = 0; i < 4; i++) {
        int m = m0 + i;
        float inv = gamma[m] * rsqrtf(var[m] + 1e-5f);
        float bsh = beta[m] - mean[m] * inv;
        float v0, v1, v2, v3;
        unpack2(acc[i][0], v0, v1);
        unpack2(acc[i][1], v2, v3);
        v0 = fmaxf(fmaf(v0, inv, bsh), 0.f);
        v1 = fmaxf(fmaf(v1, inv, bsh), 0.f);
        v2 = fmaxf(fmaf(v2, inv, bsh), 0.f);
        v3 = fmaxf(fmaf(v3, inv, bsh), 0.f);
        *(float4*)&g_xbuf[(b * 64 + m) * HW + gpix0 + p0] = make_float4(v0, v1, v2, v3);
    }
}

// ---------------------------------------------------------------------------
// Kernel 2: fused conv2 + 7x7 aggregation + residual.
// Tile = 16x8 px, 1 group, 1 batch per CTA. 256 threads, 96 KB smem, 2 CTA/SM.
// Staging via cp.async (x = group0 16B, f = group1 4B+zfill); f's latency is
// hidden under the phase-1 GEMM via wait_group 1 / wait_group 0 split.
// ---------------------------------------------------------------------------
#define TPX 128                 // pixels per tile (16 rows x 8 cols)
#define FRS 16                  // f_sh row stride (floats), rows are 14 wide
#define FCH 356                 // f_sh channel stride = 22*16 + 4 (89 chunks, odd)
#define W2S 60                  // w2_sh row stride

__global__ __launch_bounds__(256, 2)
void fused_kernel(const float* __restrict__ feat,
                  const float* __restrict__ w2,
                  const float* __restrict__ b2,
                  float* __restrict__ out)
{
    extern __shared__ float smem[];
    float* x_sh   = smem;                      // [64][128]   32768 B
    float* f_sh   = x_sh + 64 * TPX;           // 16*356 f    22784 B
    float* w2_sh  = f_sh + 16 * FCH;           // [64][60]    15360 B
    float* wgt_sh = w2_sh + 64 * W2S;          // [49][128]   25088 B  -> 96000 B

    const int tid  = threadIdx.x;
    const int g    = blockIdx.x;
    const int tile = blockIdx.y;
    const int b    = blockIdx.z;
    const int y0 = (tile >> 3) * 16;
    const int x0 = (tile & 7) * 8;
    const int w    = tid >> 5;
    const int lane = tid & 31;

    // ---- stage x tile [64 r][128 px] via cp.async 16B  (group 0)
    {
        const float* src0 = g_xbuf + (size_t)(b * 64) * HW + y0 * WDIM + x0;
        #pragma unroll
        for (int i = tid; i < 2048; i += 256) {
            int r  = i >> 5;
            int c4 = (i & 31) * 4;             // 0..124
            int row = c4 >> 3, col = c4 & 7;   // col in {0,4}
            cp_async16(smem_u32(x_sh + r * TPX + c4),
                       src0 + (size_t)r * HW + row * WDIM + col);
        }
    }
    cp_commit();

    // ---- stage feature tile + 3-px halo via cp.async 4B + zfill  (group 1)
    {
        const float* fch0 = feat + (size_t)(b * 256 + g * 16) * HW;
        for (int i = tid; i < 16 * 308; i += 256) {
            int c   = i / 308;
            int rem = i - c * 308;
            int yy  = rem / 14;
            int xx  = rem - yy * 14;
            int gy = y0 + yy - 3, gx = x0 + xx - 3;
            bool ok = ((unsigned)gy < 64u) && ((unsigned)gx < 64u);
            const float* src = fch0 + (size_t)c * HW + (ok ? gy * WDIM + gx : 0);
            cp_async4z(smem_u32(f_sh + c * FCH + yy * FRS + xx), src, ok ? 4 : 0);
        }
    }
    cp_commit();

    // ---- stage w2 (plain floats, broadcast layout [r][ (k/7)*8 + k%7 ])
    for (int i = tid; i < 49 * 64; i += 256) {
        int k = i >> 6, r = i & 63;
        int kqi = k / 7, kki = k - kqi * 7;
        w2_sh[r * W2S + kqi * 8 + kki] = w2[(g * 49 + k) * 64 + r];
    }

    asm volatile("cp.async.wait_group 1;");   // x done; f may still be in flight
    __syncthreads();

    // -------- Phase 1: wgt[49][128] = w2_g @ x + b2
    // warp = kq (7 warps; warp 7 idle), lane = 4-px chunk; 7k x 4px per thread
    if (w < 7) {
        const int kq = w;
        const int p0 = lane * 4;

        ull acc[7][2];
        #pragma unroll
        for (int kk = 0; kk < 7; kk++) {
            float bv = b2[g * 49 + kq * 7 + kk];
            ull bp = pack2(bv, bv);
            acc[kk][0] = bp; acc[kk][1] = bp;
        }
        const float* xp = x_sh + p0;
        const float* wp = w2_sh + kq * 8;
        #pragma unroll 4
        for (int r = 0; r < 64; r++) {
            ulonglong2 xv = *(const ulonglong2*)(xp + r * TPX);
            float4 wa = *(const float4*)(wp + r * W2S);       // broadcast
            float4 wb = *(const float4*)(wp + r * W2S + 4);   // broadcast
            ull t;
            t = pack2(wa.x, wa.x); fma2(acc[0][0], xv.x, t); fma2(acc[0][1], xv.y, t);
            t = pack2(wa.y, wa.y); fma2(acc[1][0], xv.x, t); fma2(acc[1][1], xv.y, t);
            t = pack2(wa.z, wa.z); fma2(acc[2][0], xv.x, t); fma2(acc[2][1], xv.y, t);
            t = pack2(wa.w, wa.w); fma2(acc[3][0], xv.x, t); fma2(acc[3][1], xv.y, t);
            t = pack2(wb.x, wb.x); fma2(acc[4][0], xv.x, t); fma2(acc[4][1], xv.y, t);
            t = pack2(wb.y, wb.y); fma2(acc[5][0], xv.x, t); fma2(acc[5][1], xv.y, t);
            t = pack2(wb.z, wb.z); fma2(acc[6][0], xv.x, t); fma2(acc[6][1], xv.y, t);
        }
        #pragma unroll
        for (int kk = 0; kk < 7; kk++) {
            int k = kq * 7 + kk;
            ull* dst = (ull*)&wgt_sh[k * TPX + p0];
            dst[0] = acc[kk][0]; dst[1] = acc[kk][1];   // STS.128, conflict-free
        }
    }

    asm volatile("cp.async.wait_group 0;");   // f tile complete (hidden under GEMM)
    __syncthreads();

    // -------- Phase 2: 7x7 dynamic aggregation + residual
    // warp covers 2 pixel rows; lane = (rowhalf, channel); 8 px x 1 ch per thread
    {
        const int rowA = 2 * w + (lane >> 4);
        const int c    = lane & 15;

        const float* fbase = f_sh + c * FCH;
        const float* wbase = wgt_sh + rowA * 8;

        float acc[8];
        #pragma unroll
        for (int j = 0; j < 8; j++) acc[j] = 0.f;

        #pragma unroll 1
        for (int di = 0; di < 7; di++) {
            float fr[16];
            #pragma unroll
            for (int q = 0; q < 4; q++)
                *(float4*)&fr[q * 4] =
                    *(const float4*)(fbase + (rowA + di) * FRS + q * 4);
            #pragma unroll
            for (int dj = 0; dj < 7; dj++) {
                int k = di * 7 + dj;
                float wv[8];
                *(float4*)&wv[0] = *(const float4*)(wbase + k * TPX);
                *(float4*)&wv[4] = *(const float4*)(wbase + k * TPX + 4);
                #pragma unroll
                for (int j = 0; j < 8; j++)
                    acc[j] = fmaf(wv[j], fr[j + dj], acc[j]);
            }
        }
        // residual + store
        #pragma unroll
        for (int j = 0; j < 8; j++)
            acc[j] += fbase[(rowA + 3) * FRS + j + 3];

        float* op = &out[(size_t)(b * 256 + g * 16 + c) * HW + (y0 + rowA) * WDIM + x0];
        *(float4*)(op)     = make_float4(acc[0], acc[1], acc[2], acc[3]);
        *(float4*)(op + 4) = make_float4(acc[4], acc[5], acc[6], acc[7]);
    }
}

// ---------------------------------------------------------------------------
extern "C" void kernel_launch(void* const* d_in, const int* in_sizes, int n_in,
                              void* d_out, int out_size)
{
    const float* feat  = (const float*)d_in[0];
    const float* guide = (const float*)d_in[1];
    const float* w1    = (const float*)d_in[2];
    const float* gamma = (const float*)d_in[3];
    const float* beta  = (const float*)d_in[4];
    const float* mean  = (const float*)d_in[5];
    const float* var   = (const float*)d_in[6];
    const float* w2    = (const float*)d_in[7];
    const float* b2    = (const float*)d_in[8];
    float* out = (float*)d_out;

    conv1_kernel<<<dim3(64, 4), 256>>>(guide, w1, gamma, beta, mean, var);

    const int smem_bytes = (64 * TPX + 16 * FCH + 64 * W2S + 49 * TPX) * 4; // 96000
    cudaFuncSetAttribute(fused_kernel,
                         cudaFuncAttributeMaxDynamicSharedMemorySize, smem_bytes);
    fused_kernel<<<dim3(16, 32, 4), 256, smem_bytes>>>(feat, w2, b2, out);
}